// round 1
// baseline (speedup 1.0000x reference)
#include <cuda_runtime.h>
#include <math.h>
#include <float.h>

// Problem constants (from reference): N=50000, E=800000, feat dims 64/128/16.
#define MAXN 50048
#define MAXE 800000
#define MAXF 128

// ---------------- scratch (static device arrays; no allocation) ----------------
__device__ float d_ew[MAXE];          // per-edge weight fc1(edge_attr)
__device__ int   d_deg[MAXN];         // in-degree histogram
__device__ int   d_rowptr[MAXN + 1];  // CSR row pointers (by dst)
__device__ int   d_cur[MAXN];         // scatter cursors
__device__ int   d_csrc[MAXE];        // CSR: src node per slot
__device__ float d_cew[MAXE];         // CSR: edge weight per slot
__device__ float d_s[MAXN];           // s_i = sum of incoming ew
__device__ int   d_bsum[64];
__device__ int   d_boff[64];
__device__ float d_A[MAXN * MAXF];    // A = h@W1 + b1   (gathered over edges)
__device__ float d_C[MAXN * MAXF];    // C = h@W3 + b3 - s*(h@W2)
__device__ float d_Ha[MAXN * MAXF];   // activations ping
__device__ float d_Hb[MAXN * MAXF];   // activations pong

// ---------------- edge preprocessing ----------------
__global__ void edge_pre(const float* __restrict__ eattr, const int* __restrict__ eidx,
                         const float* __restrict__ wfc, const float* __restrict__ bfc, int E)
{
    int e = blockIdx.x * blockDim.x + threadIdx.x;
    if (e >= E) return;
    const float4* ap = reinterpret_cast<const float4*>(eattr + e * 16);
    const float4* wp = reinterpret_cast<const float4*>(wfc);
    float4 a0 = ap[0], a1 = ap[1], a2 = ap[2], a3 = ap[3];
    float4 w0 = wp[0], w1 = wp[1], w2 = wp[2], w3 = wp[3];
    float acc = bfc[0];
    acc += a0.x * w0.x + a0.y * w0.y + a0.z * w0.z + a0.w * w0.w;
    acc += a1.x * w1.x + a1.y * w1.y + a1.z * w1.z + a1.w * w1.w;
    acc += a2.x * w2.x + a2.y * w2.y + a2.z * w2.z + a2.w * w2.w;
    acc += a3.x * w3.x + a3.y * w3.y + a3.z * w3.z + a3.w * w3.w;
    d_ew[e] = acc;
    int dst = eidx[E + e];
    atomicAdd(&d_deg[dst], 1);
    atomicAdd(&d_s[dst], acc);
}

// ---------------- scan (rowptr = exclusive scan of deg) ----------------
__global__ void scan1(int n)
{
    __shared__ int sd[1024];
    int t = threadIdx.x;
    int i = blockIdx.x * 1024 + t;
    int v = (i < n) ? d_deg[i] : 0;
    sd[t] = v;
    __syncthreads();
    for (int off = 1; off < 1024; off <<= 1) {
        int add = (t >= off) ? sd[t - off] : 0;
        __syncthreads();
        sd[t] += add;
        __syncthreads();
    }
    if (i < n) d_rowptr[i] = sd[t] - v;        // exclusive within block
    if (t == 1023) d_bsum[blockIdx.x] = sd[t]; // block total
}

__global__ void scan2(int nb)
{
    if (threadIdx.x == 0 && blockIdx.x == 0) {
        int run = 0;
        for (int b = 0; b < nb; b++) { d_boff[b] = run; run += d_bsum[b]; }
    }
}

__global__ void scan3(int n, int E)
{
    int i = blockIdx.x * 1024 + threadIdx.x;
    if (i < n) {
        int v = d_rowptr[i] + d_boff[blockIdx.x];
        d_rowptr[i] = v;
        d_cur[i] = v;
    }
    if (i == 0) d_rowptr[n] = E;
}

__global__ void scatter_k(const int* __restrict__ eidx, int E)
{
    int e = blockIdx.x * blockDim.x + threadIdx.x;
    if (e >= E) return;
    int dst = eidx[E + e];
    int pos = atomicAdd(&d_cur[dst], 1);
    d_csrc[pos] = eidx[e];
    d_cew[pos] = d_ew[e];
}

// ---------------- fused GEMM: A = H@W1+b1 ; C = H@W3+b3 - s*(H@W2) ----------------
// Block: 256 threads, 64-row tile. Thread tile 4 rows x TN cols (TN = DOUT/16).
template<int DIN, int DOUT>
__global__ __launch_bounds__(256) void gemm_fused(
    const float* __restrict__ H,
    const float* __restrict__ W1, const float* __restrict__ B1,
    const float* __restrict__ W2,
    const float* __restrict__ W3, const float* __restrict__ B3,
    int n)
{
    constexpr int BR = 64;
    constexpr int STR = BR + 4;        // padded stride (floats), keeps 16B alignment
    constexpr int TN = DOUT / 16;
    __shared__ float sh[DIN * STR];    // transposed tile: sh[k*STR + r] = H[rbase+r][k]

    int rbase = blockIdx.x * BR;
    int t = threadIdx.x;

    for (int i = t; i < BR * DIN; i += 256) {
        int r = i / DIN, k = i - r * DIN;
        int gr = rbase + r;
        float v = (gr < n) ? H[gr * DIN + k] : 0.f;
        sh[k * STR + r] = v;
    }
    __syncthreads();

    int tr = t & 15, tc = t >> 4;
    int r0 = tr * 4;
    int c0 = tc * TN;

    // ---- pass 1: W1 -> A ----
    {
        float acc[4][TN];
#pragma unroll
        for (int i = 0; i < 4; i++)
#pragma unroll
            for (int j = 0; j < TN; j++) acc[i][j] = 0.f;

#pragma unroll 4
        for (int k = 0; k < DIN; k++) {
            float4 hv = *reinterpret_cast<const float4*>(sh + k * STR + r0);
            float hvv[4] = {hv.x, hv.y, hv.z, hv.w};
            float wv[TN];
#pragma unroll
            for (int j = 0; j < TN; j += 4) {
                float4 w4 = *reinterpret_cast<const float4*>(W1 + k * DOUT + c0 + j);
                wv[j] = w4.x; wv[j + 1] = w4.y; wv[j + 2] = w4.z; wv[j + 3] = w4.w;
            }
#pragma unroll
            for (int i = 0; i < 4; i++)
#pragma unroll
                for (int j = 0; j < TN; j++)
                    acc[i][j] = fmaf(hvv[i], wv[j], acc[i][j]);
        }
        float bj[TN];
#pragma unroll
        for (int j = 0; j < TN; j++) bj[j] = B1[c0 + j];
#pragma unroll
        for (int i = 0; i < 4; i++) {
            int gr = rbase + r0 + i;
            if (gr < n) {
#pragma unroll
                for (int j = 0; j < TN; j += 4) {
                    float4 o;
                    o.x = acc[i][j]     + bj[j];
                    o.y = acc[i][j + 1] + bj[j + 1];
                    o.z = acc[i][j + 2] + bj[j + 2];
                    o.w = acc[i][j + 3] + bj[j + 3];
                    *reinterpret_cast<float4*>(&d_A[gr * DOUT + c0 + j]) = o;
                }
            }
        }
    }

    // ---- pass 2: W2 & W3 -> C ----
    {
        float a2[4][TN], a3[4][TN];
#pragma unroll
        for (int i = 0; i < 4; i++)
#pragma unroll
            for (int j = 0; j < TN; j++) { a2[i][j] = 0.f; a3[i][j] = 0.f; }

#pragma unroll 4
        for (int k = 0; k < DIN; k++) {
            float4 hv = *reinterpret_cast<const float4*>(sh + k * STR + r0);
            float hvv[4] = {hv.x, hv.y, hv.z, hv.w};
            float w2v[TN], w3v[TN];
#pragma unroll
            for (int j = 0; j < TN; j += 4) {
                float4 w4 = *reinterpret_cast<const float4*>(W2 + k * DOUT + c0 + j);
                w2v[j] = w4.x; w2v[j + 1] = w4.y; w2v[j + 2] = w4.z; w2v[j + 3] = w4.w;
                float4 u4 = *reinterpret_cast<const float4*>(W3 + k * DOUT + c0 + j);
                w3v[j] = u4.x; w3v[j + 1] = u4.y; w3v[j + 2] = u4.z; w3v[j + 3] = u4.w;
            }
#pragma unroll
            for (int i = 0; i < 4; i++)
#pragma unroll
                for (int j = 0; j < TN; j++) {
                    a2[i][j] = fmaf(hvv[i], w2v[j], a2[i][j]);
                    a3[i][j] = fmaf(hvv[i], w3v[j], a3[i][j]);
                }
        }
        float bj[TN];
#pragma unroll
        for (int j = 0; j < TN; j++) bj[j] = B3[c0 + j];
#pragma unroll
        for (int i = 0; i < 4; i++) {
            int gr = rbase + r0 + i;
            if (gr < n) {
                float sv = d_s[gr];
#pragma unroll
                for (int j = 0; j < TN; j += 4) {
                    float4 o;
                    o.x = a3[i][j]     + bj[j]     - sv * a2[i][j];
                    o.y = a3[i][j + 1] + bj[j + 1] - sv * a2[i][j + 1];
                    o.z = a3[i][j + 2] + bj[j + 2] - sv * a2[i][j + 2];
                    o.w = a3[i][j + 3] + bj[j + 3] - sv * a2[i][j + 3];
                    *reinterpret_cast<float4*>(&d_C[gr * DOUT + c0 + j]) = o;
                }
            }
        }
    }
}

// ---------------- edge aggregation + ELU: Hout = elu(C + sum_e ew*A[src]) ----------------
template<int DOUT>
__global__ __launch_bounds__(256) void agg_elu(float* __restrict__ Hout, int n)
{
    constexpr int V = DOUT / 32;   // floats per lane (2 or 4)
    int w = (blockIdx.x * blockDim.x + threadIdx.x) >> 5;
    if (w >= n) return;
    int lane = threadIdx.x & 31;
    int fo = lane * V;

    float acc[V];
    {
        const float* cp = d_C + w * DOUT + fo;
        if (V == 2) {
            float2 c = *reinterpret_cast<const float2*>(cp);
            acc[0] = c.x; acc[1] = c.y;
        } else {
            float4 c = *reinterpret_cast<const float4*>(cp);
            acc[0] = c.x; acc[1] = c.y; acc[V > 2 ? 2 : 0] = c.z; acc[V > 2 ? 3 : 0] = c.w;
            if (V == 4) { acc[0] = c.x; acc[1] = c.y; acc[2] = c.z; acc[3] = c.w; }
        }
    }

    int e = d_rowptr[w];
    int e1 = d_rowptr[w + 1];
    for (; e + 1 < e1; e += 2) {
        int   s0 = d_csrc[e],  s1 = d_csrc[e + 1];
        float w0 = d_cew[e],   w1 = d_cew[e + 1];
        const float* p0 = d_A + s0 * DOUT + fo;
        const float* p1 = d_A + s1 * DOUT + fo;
        if (V == 2) {
            float2 v0 = *reinterpret_cast<const float2*>(p0);
            float2 v1 = *reinterpret_cast<const float2*>(p1);
            acc[0] = fmaf(w0, v0.x, acc[0]); acc[1] = fmaf(w0, v0.y, acc[1]);
            acc[0] = fmaf(w1, v1.x, acc[0]); acc[1] = fmaf(w1, v1.y, acc[1]);
        } else {
            float4 v0 = *reinterpret_cast<const float4*>(p0);
            float4 v1 = *reinterpret_cast<const float4*>(p1);
            acc[0] = fmaf(w0, v0.x, acc[0]); acc[1] = fmaf(w0, v0.y, acc[1]);
            acc[2] = fmaf(w0, v0.z, acc[2]); acc[3] = fmaf(w0, v0.w, acc[3]);
            acc[0] = fmaf(w1, v1.x, acc[0]); acc[1] = fmaf(w1, v1.y, acc[1]);
            acc[2] = fmaf(w1, v1.z, acc[2]); acc[3] = fmaf(w1, v1.w, acc[3]);
        }
    }
    if (e < e1) {
        int   s0 = d_csrc[e];
        float w0 = d_cew[e];
        const float* p0 = d_A + s0 * DOUT + fo;
        if (V == 2) {
            float2 v0 = *reinterpret_cast<const float2*>(p0);
            acc[0] = fmaf(w0, v0.x, acc[0]); acc[1] = fmaf(w0, v0.y, acc[1]);
        } else {
            float4 v0 = *reinterpret_cast<const float4*>(p0);
            acc[0] = fmaf(w0, v0.x, acc[0]); acc[1] = fmaf(w0, v0.y, acc[1]);
            acc[2] = fmaf(w0, v0.z, acc[2]); acc[3] = fmaf(w0, v0.w, acc[3]);
        }
    }

#pragma unroll
    for (int v = 0; v < V; v++) {
        float xv = acc[v];
        acc[v] = xv > 0.f ? xv : expm1f(xv);
    }

    float* op = Hout + w * DOUT + fo;
    if (V == 2) {
        float2 o; o.x = acc[0]; o.y = acc[1];
        *reinterpret_cast<float2*>(op) = o;
    } else {
        float4 o; o.x = acc[0]; o.y = acc[1]; o.z = acc[2]; o.w = acc[3];
        *reinterpret_cast<float4*>(op) = o;
    }
}

// ---------------- global max pool ----------------
__device__ __forceinline__ void atomicMaxF(float* a, float v)
{
    if (v >= 0.f) atomicMax(reinterpret_cast<int*>(a), __float_as_int(v));
    else atomicMin(reinterpret_cast<unsigned int*>(a), __float_as_uint(v));
}

__global__ void pool_init(float* out, int n)
{
    int i = blockIdx.x * blockDim.x + threadIdx.x;
    if (i < n) out[i] = -FLT_MAX;
}

__global__ void pool_k(const float* __restrict__ H, const int* __restrict__ batch,
                       float* __restrict__ out, int n)
{
    int w = (blockIdx.x * blockDim.x + threadIdx.x) >> 5;
    int lane = threadIdx.x & 31;
    int node0 = w * 16;
    if (node0 >= n) return;
    int nodeE = min(node0 + 16, n);

    float mx = -FLT_MAX, my = -FLT_MAX;
    int cg = batch[node0];
    for (int nd = node0; nd < nodeE; nd++) {
        int g = batch[nd];
        if (g != cg) {
            atomicMaxF(&out[cg * 64 + lane * 2], mx);
            atomicMaxF(&out[cg * 64 + lane * 2 + 1], my);
            mx = -FLT_MAX; my = -FLT_MAX;
            cg = g;
        }
        float2 hv = *reinterpret_cast<const float2*>(H + nd * 64 + lane * 2);
        mx = fmaxf(mx, hv.x);
        my = fmaxf(my, hv.y);
    }
    atomicMaxF(&out[cg * 64 + lane * 2], mx);
    atomicMaxF(&out[cg * 64 + lane * 2 + 1], my);
}

// ---------------- launch ----------------
extern "C" void kernel_launch(void* const* d_in, const int* in_sizes, int n_in,
                              void* d_out, int out_size)
{
    const float* x     = (const float*)d_in[0];
    const int*   eidx  = (const int*)d_in[1];
    const float* eattr = (const float*)d_in[2];
    const int*   batch = (const int*)d_in[3];
    const float* wfc   = (const float*)d_in[4];
    const float* bfc   = (const float*)d_in[5];
    const float* W1_0 = (const float*)d_in[6],  *B1_0 = (const float*)d_in[7];
    const float* W2_0 = (const float*)d_in[8],  *W3_0 = (const float*)d_in[9],  *B3_0 = (const float*)d_in[10];
    const float* W1_1 = (const float*)d_in[11], *B1_1 = (const float*)d_in[12];
    const float* W2_1 = (const float*)d_in[13], *W3_1 = (const float*)d_in[14], *B3_1 = (const float*)d_in[15];
    const float* W1_2 = (const float*)d_in[16], *B1_2 = (const float*)d_in[17];
    const float* W2_2 = (const float*)d_in[18], *W3_2 = (const float*)d_in[19], *B3_2 = (const float*)d_in[20];
    float* out = (float*)d_out;

    int N = in_sizes[0] / 64;
    int E = in_sizes[1] / 2;
    if (N > MAXN) N = MAXN;
    if (E > MAXE) E = MAXE;

    float *Ha, *Hb;
    int* degp;
    float* sp;
    cudaGetSymbolAddress((void**)&Ha, d_Ha);
    cudaGetSymbolAddress((void**)&Hb, d_Hb);
    cudaGetSymbolAddress((void**)&degp, d_deg);
    cudaGetSymbolAddress((void**)&sp, d_s);

    cudaMemsetAsync(degp, 0, N * sizeof(int));
    cudaMemsetAsync(sp, 0, N * sizeof(float));

    edge_pre<<<(E + 255) / 256, 256>>>(eattr, eidx, wfc, bfc, E);

    int NB = (N + 1023) / 1024;
    scan1<<<NB, 1024>>>(N);
    scan2<<<1, 32>>>(NB);
    scan3<<<NB, 1024>>>(N, E);
    scatter_k<<<(E + 255) / 256, 256>>>(eidx, E);

    int gemm_grid = (N + 63) / 64;
    int agg_grid = (N * 32 + 255) / 256;

    // layer 0: 64 -> 64, x -> Ha
    gemm_fused<64, 64><<<gemm_grid, 256>>>(x, W1_0, B1_0, W2_0, W3_0, B3_0, N);
    agg_elu<64><<<agg_grid, 256>>>(Ha, N);

    // layer 1: 64 -> 128, Ha -> Hb
    gemm_fused<64, 128><<<gemm_grid, 256>>>(Ha, W1_1, B1_1, W2_1, W3_1, B3_1, N);
    agg_elu<128><<<agg_grid, 256>>>(Hb, N);

    // layer 2: 128 -> 64, Hb -> Ha
    gemm_fused<128, 64><<<gemm_grid, 256>>>(Hb, W1_2, B1_2, W2_2, W3_2, B3_2, N);
    agg_elu<64><<<agg_grid, 256>>>(Ha, N);

    pool_init<<<(out_size + 255) / 256, 256>>>(out, out_size);
    int pool_warps = (N + 15) / 16;
    pool_k<<<(pool_warps * 32 + 255) / 256, 256>>>(Ha, batch, out, N);
}